// round 2
// baseline (speedup 1.0000x reference)
#include <cuda_runtime.h>

// Problem constants (fixed by the reference)
#define BATCH 16384
#define DIM   2048
#define NUMCL 1000

// Scratch for per-row partial losses (allocation-free rule: __device__ global)
__device__ float g_partial[BATCH];

// ---------------------------------------------------------------------------
// Kernel 1: one warp per row.
// Computes dot(s, c), ||s||^2, ||t||^2, ||c||^2 in one fused pass over the row
// (3 float4 streams, 16 iters/lane -> high MLP, HBM-bound by design).
// ---------------------------------------------------------------------------
__global__ __launch_bounds__(256, 8)
void dnl_row_kernel(const float* __restrict__ s_emb,
                    const float* __restrict__ t_emb,
                    const float* __restrict__ T_EMB,
                    const int* __restrict__ labels)
{
    const int gwarp = (blockIdx.x * blockDim.x + threadIdx.x) >> 5;
    const int lane  = threadIdx.x & 31;
    if (gwarp >= BATCH) return;

    const size_t row_off = (size_t)gwarp * DIM;
    const float4* __restrict__ s = (const float4*)(s_emb + row_off);
    const float4* __restrict__ t = (const float4*)(t_emb + row_off);

    // JAX x64-disabled: labels are int32 despite the reference asking int64.
    // Clamp defensively so a wrong-dtype read can never produce an illegal
    // access (it would produce a clean rel_err signal instead).
    int lbl = labels[gwarp];
    lbl = (lbl < 0) ? 0 : ((lbl >= NUMCL) ? (NUMCL - 1) : lbl);
    const float4* __restrict__ c = (const float4*)(T_EMB + (size_t)lbl * DIM);

    float dot = 0.f, ss = 0.f, tt = 0.f, cc = 0.f;

    // DIM/4 = 512 float4 per row, 32 lanes -> 16 per lane
    #pragma unroll
    for (int i = 0; i < 16; ++i) {
        const int idx = i * 32 + lane;
        const float4 sv = s[idx];
        const float4 tv = t[idx];
        const float4 cv = c[idx];
        dot = fmaf(sv.x, cv.x, fmaf(sv.y, cv.y, fmaf(sv.z, cv.z, fmaf(sv.w, cv.w, dot))));
        ss  = fmaf(sv.x, sv.x, fmaf(sv.y, sv.y, fmaf(sv.z, sv.z, fmaf(sv.w, sv.w, ss))));
        tt  = fmaf(tv.x, tv.x, fmaf(tv.y, tv.y, fmaf(tv.z, tv.z, fmaf(tv.w, tv.w, tt))));
        cc  = fmaf(cv.x, cv.x, fmaf(cv.y, cv.y, fmaf(cv.z, cv.z, fmaf(cv.w, cv.w, cc))));
    }

    // Warp tree-reduce the four accumulators
    #pragma unroll
    for (int off = 16; off > 0; off >>= 1) {
        dot += __shfl_xor_sync(0xFFFFFFFFu, dot, off);
        ss  += __shfl_xor_sync(0xFFFFFFFFu, ss,  off);
        tt  += __shfl_xor_sync(0xFFFFFFFFu, tt,  off);
        cc  += __shfl_xor_sync(0xFFFFFFFFu, cc,  off);
    }

    if (lane == 0) {
        const float max_norm = fmaxf(sqrtf(ss), sqrtf(tt));
        // 1 - <s, c/||c||> / max_norm
        g_partial[gwarp] = 1.0f - dot / (sqrtf(cc) * max_norm);
    }
}

// ---------------------------------------------------------------------------
// Kernel 2: deterministic fixed-order reduction of the 16384 partials.
// Single block, 1024 threads, 16 sequential adds each, then shared tree.
// ---------------------------------------------------------------------------
__global__ __launch_bounds__(1024, 1)
void dnl_reduce_kernel(float* __restrict__ out)
{
    __shared__ float sh[1024];
    const int tid = threadIdx.x;

    float acc = 0.f;
    #pragma unroll
    for (int i = 0; i < BATCH / 1024; ++i)
        acc += g_partial[tid + i * 1024];

    sh[tid] = acc;
    __syncthreads();

    #pragma unroll
    for (int s = 512; s > 0; s >>= 1) {
        if (tid < s) sh[tid] += sh[tid + s];
        __syncthreads();
    }

    if (tid == 0)
        out[0] = sh[0] * (1.0f / (float)BATCH);  // ND_WEIGHT = 1
}

// ---------------------------------------------------------------------------
// kernel_launch: graph-capturable, allocation-free.
// Inputs (metadata order): s_emb f32[B*D], t_emb f32[B*D],
//                          T_EMB f32[NUMCL*D], labels i32[B]
// Output: f32 scalar
// ---------------------------------------------------------------------------
extern "C" void kernel_launch(void* const* d_in, const int* in_sizes, int n_in,
                              void* d_out, int out_size)
{
    const float* s_emb  = (const float*)d_in[0];
    const float* t_emb  = (const float*)d_in[1];
    const float* T_EMB  = (const float*)d_in[2];
    const int*   labels = (const int*)d_in[3];
    float* out = (float*)d_out;

    // 1 warp per row, 8 warps per block -> 2048 blocks
    const int threads = 256;
    const int blocks  = (BATCH * 32) / threads;
    dnl_row_kernel<<<blocks, threads>>>(s_emb, t_emb, T_EMB, labels);
    dnl_reduce_kernel<<<1, 1024>>>(out);
}

// round 3
// speedup vs baseline: 1.0413x; 1.0413x over previous
#include <cuda_runtime.h>

// Problem constants (fixed by the reference)
#define BATCH 16384
#define DIM   2048
#define NUMCL 1000

#define THREADS   256           // 8 warps -> 8 rows per block
#define NBLOCKS   (BATCH / 8)   // 2048 blocks

// Fused-reduction state (allocation-free rule: __device__ globals).
// g_accum must be 0 at the start of every launch; the last block resets it
// after consuming it, so the invariant holds across graph replays.
__device__ float        g_accum  = 0.0f;
__device__ unsigned int g_ticket = 0;

// ---------------------------------------------------------------------------
// Single fused kernel: one warp per row.
// Per row: dot(s,c), ||s||^2, ||t||^2, ||c||^2 in one pass (3 float4 streams,
// 16 iters/lane -> high MLP, HBM/L2-bound by design). Block-sums its 8 row
// losses, atomically accumulates, and the last-finishing block writes the
// final mean and resets state for the next replay.
// ---------------------------------------------------------------------------
__global__ __launch_bounds__(THREADS, 8)
void dnl_fused_kernel(const float* __restrict__ s_emb,
                      const float* __restrict__ t_emb,
                      const float* __restrict__ T_EMB,
                      const int*   __restrict__ labels,
                      float*       __restrict__ out)
{
    const int warp = threadIdx.x >> 5;                 // 0..7
    const int lane = threadIdx.x & 31;
    const int row  = blockIdx.x * 8 + warp;            // 0..16383

    const size_t row_off = (size_t)row * DIM;
    const float4* __restrict__ s = (const float4*)(s_emb + row_off);
    const float4* __restrict__ t = (const float4*)(t_emb + row_off);

    // labels are int32 (JAX x64-disabled downcasts the reference's int64).
    int lbl = labels[row];
    lbl = (lbl < 0) ? 0 : ((lbl >= NUMCL) ? (NUMCL - 1) : lbl);
    const float4* __restrict__ c = (const float4*)(T_EMB + (size_t)lbl * DIM);

    float dot = 0.f, ss = 0.f, tt = 0.f, cc = 0.f;

    // DIM/4 = 512 float4 per row, 32 lanes -> 16 per lane
    #pragma unroll
    for (int i = 0; i < 16; ++i) {
        const int idx = i * 32 + lane;
        const float4 sv = s[idx];
        const float4 tv = t[idx];
        const float4 cv = c[idx];
        dot = fmaf(sv.x, cv.x, fmaf(sv.y, cv.y, fmaf(sv.z, cv.z, fmaf(sv.w, cv.w, dot))));
        ss  = fmaf(sv.x, sv.x, fmaf(sv.y, sv.y, fmaf(sv.z, sv.z, fmaf(sv.w, sv.w, ss))));
        tt  = fmaf(tv.x, tv.x, fmaf(tv.y, tv.y, fmaf(tv.z, tv.z, fmaf(tv.w, tv.w, tt))));
        cc  = fmaf(cv.x, cv.x, fmaf(cv.y, cv.y, fmaf(cv.z, cv.z, fmaf(cv.w, cv.w, cc))));
    }

    // Warp tree-reduce the four accumulators
    #pragma unroll
    for (int off = 16; off > 0; off >>= 1) {
        dot += __shfl_xor_sync(0xFFFFFFFFu, dot, off);
        ss  += __shfl_xor_sync(0xFFFFFFFFu, ss,  off);
        tt  += __shfl_xor_sync(0xFFFFFFFFu, tt,  off);
        cc  += __shfl_xor_sync(0xFFFFFFFFu, cc,  off);
    }

    // Block-level: 8 per-row losses -> one sum
    __shared__ float sh_loss[8];
    if (lane == 0) {
        const float max_norm = fmaxf(sqrtf(ss), sqrtf(tt));
        sh_loss[warp] = 1.0f - dot / (sqrtf(cc) * max_norm);
    }
    __syncthreads();

    if (threadIdx.x == 0) {
        float bsum = sh_loss[0] + sh_loss[1] + sh_loss[2] + sh_loss[3]
                   + sh_loss[4] + sh_loss[5] + sh_loss[6] + sh_loss[7];
        atomicAdd(&g_accum, bsum);

        // Make the add visible before taking a ticket
        __threadfence();
        unsigned int rank = atomicInc(&g_ticket, NBLOCKS - 1);  // wraps to 0
        if (rank == NBLOCKS - 1) {
            // Last block: all adds are globally visible (each preceded by a
            // threadfence before its ticket increment).
            float total = *(volatile float*)&g_accum;
            out[0] = total * (1.0f / (float)BATCH);   // ND_WEIGHT = 1
            g_accum = 0.0f;                           // reset for next replay
        }
    }
}

// ---------------------------------------------------------------------------
// kernel_launch: graph-capturable, allocation-free, single launch.
// Inputs (metadata order): s_emb f32[B*D], t_emb f32[B*D],
//                          T_EMB f32[NUMCL*D], labels i32[B]
// Output: f32 scalar
// ---------------------------------------------------------------------------
extern "C" void kernel_launch(void* const* d_in, const int* in_sizes, int n_in,
                              void* d_out, int out_size)
{
    const float* s_emb  = (const float*)d_in[0];
    const float* t_emb  = (const float*)d_in[1];
    const float* T_EMB  = (const float*)d_in[2];
    const int*   labels = (const int*)d_in[3];
    float* out = (float*)d_out;

    dnl_fused_kernel<<<NBLOCKS, THREADS>>>(s_emb, t_emb, T_EMB, labels, out);
}

// round 4
// speedup vs baseline: 1.0861x; 1.0430x over previous
#include <cuda_runtime.h>

// Problem constants (fixed by the reference)
#define BATCH 16384
#define DIM   2048
#define NUMCL 1000

#define THREADS   256           // 8 warps -> 8 rows per block
#define NBLOCKS   (BATCH / 8)   // 2048 blocks

// Fused-reduction state (allocation-free rule: __device__ globals).
__device__ float        g_accum  = 0.0f;
__device__ unsigned int g_ticket = 0;

// ---------------------------------------------------------------------------
// Single fused kernel: one warp per row.
// s/t are 256 MB of stream-once data -> load with .cs (evict-first) so they
// don't thrash the 8 MB T_EMB working set out of L2. c loads stay default
// (evict-normal) so gathered class centers remain L2-resident.
// ---------------------------------------------------------------------------
__global__ __launch_bounds__(THREADS, 8)
void dnl_fused_kernel(const float* __restrict__ s_emb,
                      const float* __restrict__ t_emb,
                      const float* __restrict__ T_EMB,
                      const int*   __restrict__ labels,
                      float*       __restrict__ out)
{
    const int warp = threadIdx.x >> 5;                 // 0..7
    const int lane = threadIdx.x & 31;
    const int row  = blockIdx.x * 8 + warp;            // 0..16383

    const size_t row_off = (size_t)row * DIM;
    const float4* __restrict__ s = (const float4*)(s_emb + row_off);
    const float4* __restrict__ t = (const float4*)(t_emb + row_off);

    // labels are int32 (JAX x64-disabled downcasts the reference's int64).
    int lbl = labels[row];
    lbl = (lbl < 0) ? 0 : ((lbl >= NUMCL) ? (NUMCL - 1) : lbl);
    const float4* __restrict__ c = (const float4*)(T_EMB + (size_t)lbl * DIM);

    float dot = 0.f, ss = 0.f, tt = 0.f, cc = 0.f;

    // DIM/4 = 512 float4 per row, 32 lanes -> 16 per lane
    #pragma unroll
    for (int i = 0; i < 16; ++i) {
        const int idx = i * 32 + lane;
        const float4 sv = __ldcs(&s[idx]);   // streaming: evict-first
        const float4 tv = __ldcs(&t[idx]);   // streaming: evict-first
        const float4 cv = c[idx];            // reused across rows: keep in L2
        dot = fmaf(sv.x, cv.x, fmaf(sv.y, cv.y, fmaf(sv.z, cv.z, fmaf(sv.w, cv.w, dot))));
        ss  = fmaf(sv.x, sv.x, fmaf(sv.y, sv.y, fmaf(sv.z, sv.z, fmaf(sv.w, sv.w, ss))));
        tt  = fmaf(tv.x, tv.x, fmaf(tv.y, tv.y, fmaf(tv.z, tv.z, fmaf(tv.w, tv.w, tt))));
        cc  = fmaf(cv.x, cv.x, fmaf(cv.y, cv.y, fmaf(cv.z, cv.z, fmaf(cv.w, cv.w, cc))));
    }

    // Warp tree-reduce the four accumulators
    #pragma unroll
    for (int off = 16; off > 0; off >>= 1) {
        dot += __shfl_xor_sync(0xFFFFFFFFu, dot, off);
        ss  += __shfl_xor_sync(0xFFFFFFFFu, ss,  off);
        tt  += __shfl_xor_sync(0xFFFFFFFFu, tt,  off);
        cc  += __shfl_xor_sync(0xFFFFFFFFu, cc,  off);
    }

    // Block-level: 8 per-row losses -> one sum
    __shared__ float sh_loss[8];
    if (lane == 0) {
        const float max_norm = fmaxf(sqrtf(ss), sqrtf(tt));
        sh_loss[warp] = 1.0f - dot / (sqrtf(cc) * max_norm);
    }
    __syncthreads();

    if (threadIdx.x == 0) {
        float bsum = sh_loss[0] + sh_loss[1] + sh_loss[2] + sh_loss[3]
                   + sh_loss[4] + sh_loss[5] + sh_loss[6] + sh_loss[7];
        atomicAdd(&g_accum, bsum);

        // Make the add visible before taking a ticket
        __threadfence();
        unsigned int rank = atomicInc(&g_ticket, NBLOCKS - 1);  // wraps to 0
        if (rank == NBLOCKS - 1) {
            float total = *(volatile float*)&g_accum;
            out[0] = total * (1.0f / (float)BATCH);   // ND_WEIGHT = 1
            g_accum = 0.0f;                           // reset for next replay
        }
    }
}

// ---------------------------------------------------------------------------
// kernel_launch: graph-capturable, allocation-free, single launch.
// Inputs (metadata order): s_emb f32[B*D], t_emb f32[B*D],
//                          T_EMB f32[NUMCL*D], labels i32[B]
// Output: f32 scalar
// ---------------------------------------------------------------------------
extern "C" void kernel_launch(void* const* d_in, const int* in_sizes, int n_in,
                              void* d_out, int out_size)
{
    const float* s_emb  = (const float*)d_in[0];
    const float* t_emb  = (const float*)d_in[1];
    const float* T_EMB  = (const float*)d_in[2];
    const int*   labels = (const int*)d_in[3];
    float* out = (float*)d_out;

    dnl_fused_kernel<<<NBLOCKS, THREADS>>>(s_emb, t_emb, T_EMB, labels, out);
}